// round 6
// baseline (speedup 1.0000x reference)
#include <cuda_runtime.h>
#include <cstdint>

#define T_STEPS 1000
#define BATCH   8192
#define IN      9
#define HID     96
#define OUTD    3
#define HS      12   // hidden units per lane-slice
#define HP      6    // f32x2 pairs per lane-slice
#define EPT     2    // batch elements per thread

typedef unsigned long long u64;

union f2u {
    u64 u;
    float f[2];
};

__device__ __forceinline__ u64 pack2(float lo, float hi) {
    f2u v; v.f[0] = lo; v.f[1] = hi; return v.u;
}
__device__ __forceinline__ u64 ffma2(u64 a, u64 b, u64 c) {
    u64 d;
    asm("fma.rn.f32x2 %0, %1, %2, %3;" : "=l"(d) : "l"(a), "l"(b), "l"(c));
    return d;
}

__global__ __launch_bounds__(256, 1)
void snn_kernel(const float* __restrict__ X,
                const float* __restrict__ W1,
                const float* __restrict__ B1,
                const float* __restrict__ W2,
                const float* __restrict__ B2,
                float* __restrict__ out)
{
    const int tid  = blockIdx.x * 256 + threadIdx.x;   // 0..32767
    const int pos  = tid & 7;                          // lane within 8-thread group
    const int b0   = (tid >> 3) * EPT;                 // first batch element
    const int hbase = pos * HS;

    // ---- Weight slices to registers (shared by both elements): 156 regs ----
    u64 w1p[IN][HP];
#pragma unroll
    for (int j = 0; j < HP; j++) {
        const int h0 = hbase + 2 * j;
#pragma unroll
        for (int i = 0; i < IN; i++)
            w1p[i][j] = pack2(W1[h0 * IN + i], W1[(h0 + 1) * IN + i]);
    }
    u64 b1p[HP];
#pragma unroll
    for (int j = 0; j < HP; j++)
        b1p[j] = pack2(B1[hbase + 2 * j], B1[hbase + 2 * j + 1]);

    u64 w2p[OUTD][HP];
#pragma unroll
    for (int o = 0; o < OUTD; o++)
#pragma unroll
        for (int j = 0; j < HP; j++)
            w2p[o][j] = pack2(W2[o * HID + hbase + 2 * j],
                              W2[o * HID + hbase + 2 * j + 1]);

    const float b2r0 = B2[0], b2r1 = B2[1], b2r2 = B2[2];

    const u64 BETA2  = 0x3F6B851F3F6B851Full;  // {0.92, 0.92}
    const float NEGINVB = -(1.0f / 0.92f);
    u64 NEGINVB2;
    { f2u v; v.f[0] = NEGINVB; v.f[1] = NEGINVB; NEGINVB2 = v.u; }

    // ---- State (m-tilde fold: m~ = m - s/beta, so m_t = beta*m~ + cur) ----
    u64 mt[EPT][HP];
#pragma unroll
    for (int e = 0; e < EPT; e++)
#pragma unroll
        for (int j = 0; j < HP; j++) mt[e][j] = 0ull;

    float m2[EPT][OUTD], s2[EPT][OUTD];
#pragma unroll
    for (int e = 0; e < EPT; e++)
#pragma unroll
        for (int k = 0; k < OUTD; k++) { m2[e][k] = 0.f; s2[e][k] = 0.f; }

    const int xstride = BATCH * IN;     // 73728
    const int orow    = BATCH * OUTD;   // 24576
    const int memoff  = T_STEPS * orow;

    const float* xp[EPT];
    float* stp[EPT];
#pragma unroll
    for (int e = 0; e < EPT; e++) {
        xp[e]  = X + (b0 + e) * IN;
        stp[e] = out + (b0 + e) * OUTD
               + ((pos < 3) ? pos : pos - 3)
               + ((pos < 3) ? 0 : memoff);
    }

    // prefetch x for t=0
    float nx[EPT][IN];
#pragma unroll
    for (int e = 0; e < EPT; e++)
#pragma unroll
        for (int i = 0; i < IN; i++) nx[e][i] = __ldg(xp[e] + i);

#pragma unroll 1
    for (int t = 0; t < T_STEPS; t++) {
        float r[EPT][OUTD];

#pragma unroll
        for (int e = 0; e < EPT; e++) {
            // layer 1: m = beta*m~ + b1 + x@W1slice
            u64 mp[HP];
#pragma unroll
            for (int j = 0; j < HP; j++)
                mp[j] = ffma2(BETA2, mt[e][j], b1p[j]);
#pragma unroll
            for (int i = 0; i < IN; i++) {
                const u64 xd = pack2(nx[e][i], nx[e][i]);
#pragma unroll
                for (int j = 0; j < HP; j++)
                    mp[j] = ffma2(xd, w1p[i][j], mp[j]);
            }

            // spike, fold reset into state, layer-2 partials
            u64 c0 = 0ull, c1 = 0ull, c2 = 0ull;
#pragma unroll
            for (int j = 0; j < HP; j++) {
                f2u m; m.u = mp[j];
                const float sa = (m.f[0] > 1.0f) ? 1.0f : 0.0f;
                const float sb = (m.f[1] > 1.0f) ? 1.0f : 0.0f;
                const u64 s = pack2(sa, sb);
                mt[e][j] = ffma2(s, NEGINVB2, mp[j]);
                c0 = ffma2(s, w2p[0][j], c0);
                c1 = ffma2(s, w2p[1][j], c1);
                c2 = ffma2(s, w2p[2][j], c2);
            }
            f2u a0, a1, a2;
            a0.u = c0; a1.u = c1; a2.u = c2;
            r[e][0] = a0.f[0] + a0.f[1];
            r[e][1] = a1.f[0] + a1.f[1];
            r[e][2] = a2.f[0] + a2.f[1];
        }

        // prefetch next timestep's x (overlaps reduction below)
        if (t + 1 < T_STEPS) {
#pragma unroll
            for (int e = 0; e < EPT; e++) {
                const float* nxt = xp[e] + (t + 1) * xstride;
#pragma unroll
                for (int i = 0; i < IN; i++) nx[e][i] = __ldg(nxt + i);
            }
        }

        // butterfly reduction over the 8-lane group, both elems interleaved
#pragma unroll
        for (int lvl = 1; lvl <= 4; lvl <<= 1) {
#pragma unroll
            for (int e = 0; e < EPT; e++) {
#pragma unroll
                for (int k = 0; k < OUTD; k++)
                    r[e][k] += __shfl_xor_sync(0xffffffffu, r[e][k], lvl);
            }
        }

        // mem2 update + distributed store
#pragma unroll
        for (int e = 0; e < EPT; e++) {
            const float bb[OUTD] = { b2r0, b2r1, b2r2 };
#pragma unroll
            for (int k = 0; k < OUTD; k++) {
                m2[e][k] = fmaf(0.92f, m2[e][k], r[e][k] + bb[k]) - s2[e][k];
                s2[e][k] = (m2[e][k] > 1.0f) ? 1.0f : 0.0f;
            }
            float val = s2[e][0];
            val = (pos == 1) ? s2[e][1] : val;
            val = (pos == 2) ? s2[e][2] : val;
            val = (pos == 3) ? m2[e][0] : val;
            val = (pos == 4) ? m2[e][1] : val;
            val = (pos == 5) ? m2[e][2] : val;
            if (pos < 6) *stp[e] = val;
            stp[e] += orow;
        }
    }
}

extern "C" void kernel_launch(void* const* d_in, const int* in_sizes, int n_in,
                              void* d_out, int out_size)
{
    const float* X  = (const float*)d_in[0];
    const float* W1 = (const float*)d_in[1];
    const float* B1 = (const float*)d_in[2];
    const float* W2 = (const float*)d_in[3];
    const float* B2 = (const float*)d_in[4];
    float* out = (float*)d_out;

    // 32768 threads total: 8192 batches x 8 lanes / 2 elems-per-thread.
    // 128 blocks x 256 threads, 1 block/SM -> single wave, balanced.
    snn_kernel<<<128, 256>>>(X, W1, B1, W2, B2, out);
}

// round 8
// speedup vs baseline: 1.4112x; 1.4112x over previous
#include <cuda_runtime.h>
#include <cstdint>

#define T_STEPS 1000
#define BATCH   8192
#define IN      9
#define HID     96
#define OUTD    3
#define GRP     16
#define HS      6
#define HP      3
#define CH      10                  // timesteps per staged chunk
#define NC      (T_STEPS / CH)      // 100 chunks
#define BPB     8                   // batches per block (128 threads / 16)
#define CHF     (CH * BPB * IN)     // u64 slots per chunk per block = 720
#define NLD     6                   // ceil(720/128)

typedef unsigned long long u64;

union f2u {
    u64 u;
    float f[2];
};

__device__ __forceinline__ u64 pack2(float lo, float hi) {
    f2u v; v.f[0] = lo; v.f[1] = hi; return v.u;
}
__device__ __forceinline__ u64 ffma2(u64 a, u64 b, u64 c) {
    u64 d;
    asm("fma.rn.f32x2 %0, %1, %2, %3;" : "=l"(d) : "l"(a), "l"(b), "l"(c));
    return d;
}

__global__ __launch_bounds__(128, 4)
void snn_kernel(const float* __restrict__ X,
                const float* __restrict__ W1,
                const float* __restrict__ B1,
                const float* __restrict__ W2,
                const float* __restrict__ B2,
                float* __restrict__ out)
{
    __shared__ u64 xs[2][CHF];     // x staged pre-duplicated as {f,f}

    const int tix  = threadIdx.x;
    const int pos  = tix & 15;                 // lane within 16-thread group
    const int bl   = tix >> 4;                 // local batch 0..7
    const int b    = blockIdx.x * BPB + bl;    // global batch element
    const int hbase = pos * HS;
    const int p3   = (pos < 3) ? pos : pos - 3;

    // ---- Weight slices to registers ----
    u64 w1p[IN][HP];
#pragma unroll
    for (int j = 0; j < HP; j++) {
        const int h0 = hbase + 2 * j;
#pragma unroll
        for (int i = 0; i < IN; i++)
            w1p[i][j] = pack2(W1[h0 * IN + i], W1[(h0 + 1) * IN + i]);
    }
    u64 b1p[HP];
#pragma unroll
    for (int j = 0; j < HP; j++)
        b1p[j] = pack2(B1[hbase + 2 * j], B1[hbase + 2 * j + 1]);

    u64 w2p[OUTD][HP];
#pragma unroll
    for (int o = 0; o < OUTD; o++)
#pragma unroll
        for (int j = 0; j < HP; j++)
            w2p[o][j] = pack2(W2[o * HID + hbase + 2 * j],
                              W2[o * HID + hbase + 2 * j + 1]);

    // per-lane layer-2 bias (lane tracks exactly one output channel)
    const float bk = B2[p3 % OUTD];

    const u64 BETA2 = 0x3F6B851F3F6B851Full;   // {0.92, 0.92}
    u64 NEGINVB2;
    { f2u v; v.f[0] = -(1.0f / 0.92f); v.f[1] = v.f[0]; NEGINVB2 = v.u; }

    // ---- State (tilde fold: m~ = m - s/beta => m_t = beta*m~ + cur) ----
    u64 mt[HP];
#pragma unroll
    for (int j = 0; j < HP; j++) mt[j] = 0ull;
    float mloc = 0.f, sloc = 0.f;   // this lane's mem2 channel

    const int orow   = BATCH * OUTD;         // 24576
    const int memoff = T_STEPS * orow;
    const int cstride = CH * BATCH * IN;     // global floats per chunk

    float* stp = out + b * OUTD + p3 + ((pos < 3) ? 0 : memoff);

    // ---- Cooperative-load offsets (computed once) ----
    int offk[NLD];
#pragma unroll
    for (int k = 0; k < NLD; k++) {
        const int j = tix + 128 * k;          // 0..767 (valid < 720)
        const int tl = j / (BPB * IN);        // timestep-in-chunk
        const int rem = j - tl * (BPB * IN);
        offk[k] = tl * (BATCH * IN) + blockIdx.x * (BPB * IN) + rem;
    }

    // ---- Prologue: stage chunk 0 ----
    float stage[NLD];
#pragma unroll
    for (int k = 0; k < NLD; k++)
        if (tix + 128 * k < CHF) stage[k] = __ldg(X + offk[k]);
#pragma unroll
    for (int k = 0; k < NLD; k++)
        if (tix + 128 * k < CHF) xs[0][tix + 128 * k] = pack2(stage[k], stage[k]);
    __syncthreads();

#pragma unroll 1
    for (int c = 0; c < NC; c++) {
        // issue next chunk's loads early (overlap with compute)
        const bool more = (c + 1 < NC);
        if (more) {
            const float* xb = X + (c + 1) * cstride;
#pragma unroll
            for (int k = 0; k < NLD; k++)
                if (tix + 128 * k < CHF) stage[k] = __ldg(xb + offk[k]);
        }

        const u64* xrow = &xs[c & 1][bl * IN];

#pragma unroll 1
        for (int s = 0; s < CH; s++) {
            // layer 1: m = beta*m~ + b1 + x@W1slice
            u64 mp[HP];
#pragma unroll
            for (int j = 0; j < HP; j++)
                mp[j] = ffma2(BETA2, mt[j], b1p[j]);
#pragma unroll
            for (int i = 0; i < IN; i++) {
                const u64 xd = xrow[i];
#pragma unroll
                for (int j = 0; j < HP; j++)
                    mp[j] = ffma2(xd, w1p[i][j], mp[j]);
            }
            xrow += BPB * IN;

            // spike + fold reset into state + layer-2 partials
            u64 c0 = 0ull, c1 = 0ull, c2 = 0ull;
#pragma unroll
            for (int j = 0; j < HP; j++) {
                f2u m; m.u = mp[j];
                f2u sv;
                sv.f[0] = (m.f[0] > 1.0f) ? 1.0f : 0.0f;
                sv.f[1] = (m.f[1] > 1.0f) ? 1.0f : 0.0f;
                mt[j] = ffma2(sv.u, NEGINVB2, mp[j]);
                c0 = ffma2(sv.u, w2p[0][j], c0);
                c1 = ffma2(sv.u, w2p[1][j], c1);
                c2 = ffma2(sv.u, w2p[2][j], c2);
            }
            f2u a0, a1, a2;
            a0.u = c0; a1.u = c1; a2.u = c2;
            float r0 = a0.f[0] + a0.f[1];
            float r1 = a1.f[0] + a1.f[1];
            float r2 = a2.f[0] + a2.f[1];

            // butterfly reduction across the 16-lane group (3 indep chains)
            r0 += __shfl_xor_sync(0xffffffffu, r0, 1);
            r1 += __shfl_xor_sync(0xffffffffu, r1, 1);
            r2 += __shfl_xor_sync(0xffffffffu, r2, 1);
            r0 += __shfl_xor_sync(0xffffffffu, r0, 2);
            r1 += __shfl_xor_sync(0xffffffffu, r1, 2);
            r2 += __shfl_xor_sync(0xffffffffu, r2, 2);
            r0 += __shfl_xor_sync(0xffffffffu, r0, 4);
            r1 += __shfl_xor_sync(0xffffffffu, r1, 4);
            r2 += __shfl_xor_sync(0xffffffffu, r2, 4);
            r0 += __shfl_xor_sync(0xffffffffu, r0, 8);
            r1 += __shfl_xor_sync(0xffffffffu, r1, 8);
            r2 += __shfl_xor_sync(0xffffffffu, r2, 8);

            // per-lane mem2: this lane tracks one output channel only
            float rk = r0;
            rk = (p3 == 1) ? r1 : rk;
            rk = (p3 == 2) ? r2 : rk;
            mloc = fmaf(0.92f, mloc, rk + bk) - sloc;
            sloc = (mloc > 1.0f) ? 1.0f : 0.0f;

            const float val = (pos < 3) ? sloc : mloc;
            if (pos < 6) *stp = val;
            stp += orow;
        }

        // commit next chunk into the other buffer, then block-sync
        if (more) {
#pragma unroll
            for (int k = 0; k < NLD; k++)
                if (tix + 128 * k < CHF)
                    xs[(c + 1) & 1][tix + 128 * k] = pack2(stage[k], stage[k]);
            __syncthreads();
        }
    }
}

extern "C" void kernel_launch(void* const* d_in, const int* in_sizes, int n_in,
                              void* d_out, int out_size)
{
    const float* X  = (const float*)d_in[0];
    const float* W1 = (const float*)d_in[1];
    const float* B1 = (const float*)d_in[2];
    const float* W2 = (const float*)d_in[3];
    const float* B2 = (const float*)d_in[4];
    float* out = (float*)d_out;

    snn_kernel<<<BATCH / BPB, 128>>>(X, W1, B1, W2, B2, out);  // 1024 blocks
}

// round 9
// speedup vs baseline: 1.4702x; 1.0418x over previous
#include <cuda_runtime.h>
#include <cstdint>

#define T_STEPS 1000
#define BATCH   8192
#define IN      9
#define HID     96
#define OUTD    3
#define GRP     16
#define HS      6
#define HP      3
#define CH      10                   // timesteps per staged chunk
#define NC      (T_STEPS / CH)       // 100 chunks
#define BPB     8                    // batches per block
#define ROWP    10                   // padded u64 slots per (t, batch) row
#define CHF     (CH * BPB * IN)      // valid elements per chunk = 720
#define NLD     6                    // ceil(720/128)

typedef unsigned long long u64;

union f2u {
    u64 u;
    float f[2];
};

__device__ __forceinline__ u64 pack2(float lo, float hi) {
    f2u v; v.f[0] = lo; v.f[1] = hi; return v.u;
}
__device__ __forceinline__ u64 ffma2(u64 a, u64 b, u64 c) {
    u64 d;
    asm("fma.rn.f32x2 %0, %1, %2, %3;" : "=l"(d) : "l"(a), "l"(b), "l"(c));
    return d;
}

__global__ __launch_bounds__(128, 4)
void snn_kernel(const float* __restrict__ X,
                const float* __restrict__ W1,
                const float* __restrict__ B1,
                const float* __restrict__ W2,
                const float* __restrict__ B2,
                float* __restrict__ out)
{
    __shared__ alignas(16) u64 xs[2][CH * BPB * ROWP];  // x pre-duplicated {f,f}

    const int tix  = threadIdx.x;
    const int pos  = tix & 15;                 // lane within 16-thread group
    const int bl   = tix >> 4;                 // local batch 0..7
    const int b    = blockIdx.x * BPB + bl;    // global batch element
    const int hbase = pos * HS;
    const int ch   = pos & 3;                  // this lane's output channel (3 = idle)
    const int chc  = (ch < 3) ? ch : 2;        // clamped for safe indexing

    // ---- Weight slices to registers ----
    u64 w1p[IN][HP];
#pragma unroll
    for (int j = 0; j < HP; j++) {
        const int h0 = hbase + 2 * j;
#pragma unroll
        for (int i = 0; i < IN; i++)
            w1p[i][j] = pack2(W1[h0 * IN + i], W1[(h0 + 1) * IN + i]);
    }
    u64 b1p[HP];
#pragma unroll
    for (int j = 0; j < HP; j++)
        b1p[j] = pack2(B1[hbase + 2 * j], B1[hbase + 2 * j + 1]);

    u64 w2p[OUTD][HP];
#pragma unroll
    for (int o = 0; o < OUTD; o++)
#pragma unroll
        for (int j = 0; j < HP; j++)
            w2p[o][j] = pack2(W2[o * HID + hbase + 2 * j],
                              W2[o * HID + hbase + 2 * j + 1]);

    const float bk = B2[chc];

    const u64 BETA2 = 0x3F6B851F3F6B851Full;   // {0.92, 0.92}
    u64 NEGINVB2;
    { f2u v; v.f[0] = -(1.0f / 0.92f); v.f[1] = v.f[0]; NEGINVB2 = v.u; }

    // ---- State ----
    u64 mt[HP];
#pragma unroll
    for (int j = 0; j < HP; j++) mt[j] = 0ull;
    float mloc = 0.f, sloc = 0.f;

    const int orow    = BATCH * OUTD;          // 24576
    const int memoff  = T_STEPS * orow;
    const int cstride = CH * BATCH * IN;

    // writer lanes: pos 0-2 -> spk2[ch], pos 4-6 -> mem2[ch]
    const bool writer = (ch < 3) && (pos < 8);
    const bool is_spk = (pos < 4);
    float* stp = out + b * OUTD + chc + (is_spk ? 0 : memoff);

    // ---- Cooperative-load offsets + padded smem slots (computed once) ----
    int offk[NLD], slotk[NLD];
#pragma unroll
    for (int k = 0; k < NLD; k++) {
        const int j   = tix + 128 * k;         // 0..767 (valid < 720)
        const int tl  = j / (BPB * IN);
        const int rem = j - tl * (BPB * IN);
        const int bll = rem / IN;
        const int ii  = rem - bll * IN;
        offk[k]  = tl * (BATCH * IN) + blockIdx.x * (BPB * IN) + rem;
        slotk[k] = (tl * BPB + bll) * ROWP + ii;
    }

    // ---- Prologue: stage chunk 0 ----
    float stage[NLD];
#pragma unroll
    for (int k = 0; k < NLD; k++)
        if (tix + 128 * k < CHF) stage[k] = __ldg(X + offk[k]);
#pragma unroll
    for (int k = 0; k < NLD; k++)
        if (tix + 128 * k < CHF) xs[0][slotk[k]] = pack2(stage[k], stage[k]);
    __syncthreads();

#pragma unroll 1
    for (int c = 0; c < NC; c++) {
        const bool more = (c + 1 < NC);
        if (more) {
            const float* xb = X + (c + 1) * cstride;
#pragma unroll
            for (int k = 0; k < NLD; k++)
                if (tix + 128 * k < CHF) stage[k] = __ldg(xb + offk[k]);
        }

        const u64* xrow = &xs[c & 1][bl * ROWP];

#pragma unroll 2
        for (int s = 0; s < CH; s++) {
            // layer 1: m = beta*m~ + b1 + x@W1slice
            u64 mp[HP];
#pragma unroll
            for (int j = 0; j < HP; j++)
                mp[j] = ffma2(BETA2, mt[j], b1p[j]);
#pragma unroll
            for (int i = 0; i < IN; i++) {
                const u64 xd = xrow[i];
#pragma unroll
                for (int j = 0; j < HP; j++)
                    mp[j] = ffma2(xd, w1p[i][j], mp[j]);
            }
            xrow += BPB * ROWP;

            // spike + reset fold + layer-2 partials
            u64 c0 = 0ull, c1 = 0ull, c2 = 0ull;
#pragma unroll
            for (int j = 0; j < HP; j++) {
                f2u m; m.u = mp[j];
                f2u sv;
                sv.f[0] = (m.f[0] > 1.0f) ? 1.0f : 0.0f;
                sv.f[1] = (m.f[1] > 1.0f) ? 1.0f : 0.0f;
                mt[j] = ffma2(sv.u, NEGINVB2, mp[j]);
                c0 = ffma2(sv.u, w2p[0][j], c0);
                c1 = ffma2(sv.u, w2p[1][j], c1);
                c2 = ffma2(sv.u, w2p[2][j], c2);
            }
            f2u a0, a1, a2;
            a0.u = c0; a1.u = c1; a2.u = c2;
            float r0 = a0.f[0] + a0.f[1];
            float r1 = a1.f[0] + a1.f[1];
            float r2 = a2.f[0] + a2.f[1];

            // levels 1,2: all channels (quad sums)
            r0 += __shfl_xor_sync(0xffffffffu, r0, 1);
            r1 += __shfl_xor_sync(0xffffffffu, r1, 1);
            r2 += __shfl_xor_sync(0xffffffffu, r2, 1);
            r0 += __shfl_xor_sync(0xffffffffu, r0, 2);
            r1 += __shfl_xor_sync(0xffffffffu, r1, 2);
            r2 += __shfl_xor_sync(0xffffffffu, r2, 2);

            // select own channel (pos&3 invariant under xor 4/8), finish
            float v = r0;
            v = (ch == 1) ? r1 : v;
            v = (ch == 2) ? r2 : v;
            v += __shfl_xor_sync(0xffffffffu, v, 4);
            v += __shfl_xor_sync(0xffffffffu, v, 8);

            // per-lane mem2 for this lane's channel
            mloc = fmaf(0.92f, mloc, v + bk) - sloc;
            sloc = (mloc > 1.0f) ? 1.0f : 0.0f;

            if (writer) *stp = is_spk ? sloc : mloc;
            stp += orow;
        }

        if (more) {
#pragma unroll
            for (int k = 0; k < NLD; k++)
                if (tix + 128 * k < CHF)
                    xs[(c + 1) & 1][slotk[k]] = pack2(stage[k], stage[k]);
            __syncthreads();
        }
    }
}

extern "C" void kernel_launch(void* const* d_in, const int* in_sizes, int n_in,
                              void* d_out, int out_size)
{
    const float* X  = (const float*)d_in[0];
    const float* W1 = (const float*)d_in[1];
    const float* B1 = (const float*)d_in[2];
    const float* W2 = (const float*)d_in[3];
    const float* B2 = (const float*)d_in[4];
    float* out = (float*)d_out;

    snn_kernel<<<BATCH / BPB, 128>>>(X, W1, B1, W2, B2, out);  // 1024 blocks
}